// round 5
// baseline (speedup 1.0000x reference)
#include <cuda_runtime.h>
#include <math.h>

// ---------------- problem constants ----------------
#define B_   4
#define F_   256
#define N0_  128
#define N1_  128
#define N_   256        // nodes per graph
#define BN_  1024       // total nodes
#define L_   3

#define ASTR 20         // smem stride for A tile (64 x 16), conflict-free + 16B aligned
#define BSTR 72         // smem stride for B tile (16 x 64), conflict-free + 16B aligned

// ---------------- scratch (device globals; no allocation) ----------------
__device__ float g_x[BN_ * F_];
__device__ float g_H[2 * BN_ * F_];
__device__ float g_qs[2 * BN_];
__device__ float g_ks[2 * BN_];
__device__ float g_alpha[B_ * N_ * N_];
__device__ float g_msg1[BN_ * F_];
__device__ float g_msg2[BN_ * F_];
__device__ float g_lwT[2 * F_ * F_];
__device__ float g_sum[F_];
__device__ float g_sum2[F_];
__device__ float g_mu[F_];
__device__ float g_rstd[F_];

// ---------------- tf32 helpers ----------------
__device__ __forceinline__ unsigned f2tf(float f) {
    unsigned u;
    asm("cvt.rna.tf32.f32 %0, %1;" : "=r"(u) : "f"(f));
    return u;
}

__device__ __forceinline__ void mma8(float* d, const unsigned* a, const unsigned* b) {
    asm volatile(
        "mma.sync.aligned.m16n8k8.row.col.f32.tf32.tf32.f32 "
        "{%0,%1,%2,%3},{%4,%5,%6,%7},{%8,%9},{%0,%1,%2,%3};\n"
        : "+f"(d[0]), "+f"(d[1]), "+f"(d[2]), "+f"(d[3])
        : "r"(a[0]), "r"(a[1]), "r"(a[2]), "r"(a[3]), "r"(b[0]), "r"(b[1]));
}

// 64x64 block tile, 4 warps (warp tile 32x32 = 2 m-frags x 4 n-frags), BK=16
__device__ __forceinline__ void compute_bk(const unsigned* As, const unsigned* Bs,
                                           float acc[2][4][4], int lane, int wm, int wn) {
    int g = lane >> 2, tg = lane & 3;
#pragma unroll
    for (int s = 0; s < 2; s++) {
        int kb = s * 8;
        unsigned a[2][4], b[4][2];
#pragma unroll
        for (int i = 0; i < 2; i++) {
            int r0 = wm + i * 16 + g;
            a[i][0] = As[r0 * ASTR + kb + tg];
            a[i][1] = As[(r0 + 8) * ASTR + kb + tg];
            a[i][2] = As[r0 * ASTR + kb + tg + 4];
            a[i][3] = As[(r0 + 8) * ASTR + kb + tg + 4];
        }
#pragma unroll
        for (int j = 0; j < 4; j++) {
            b[j][0] = Bs[(kb + tg) * BSTR + wn + j * 8 + g];
            b[j][1] = Bs[(kb + tg + 4) * BSTR + wn + j * 8 + g];
        }
#pragma unroll
        for (int i = 0; i < 2; i++)
#pragma unroll
            for (int j = 0; j < 4; j++) mma8(acc[i][j], a[i], b[j]);
    }
}

__device__ __forceinline__ void store_tiles(unsigned* Asm, unsigned* Bsm,
                                            const float4* ra, const float4* rb, int t) {
#pragma unroll
    for (int u = 0; u < 2; u++) {
        int idx = t * 2 + u;
        {
            int row = idx >> 2, c4 = (idx & 3) * 4;
            uint4 w = make_uint4(f2tf(ra[u].x), f2tf(ra[u].y), f2tf(ra[u].z), f2tf(ra[u].w));
            *(uint4*)&Asm[row * ASTR + c4] = w;
        }
        {
            int row = idx >> 4, c4 = (idx & 15) * 4;
            uint4 w = make_uint4(f2tf(rb[u].x), f2tf(rb[u].y), f2tf(rb[u].z), f2tf(rb[u].w));
            *(uint4*)&Bsm[row * BSTR + c4] = w;
        }
    }
}

// ---------------- pack (+zero accumulators for layer 0) ----------------
__global__ void pack_kernel(const float* __restrict__ d0, const float* __restrict__ d1) {
    int b = blockIdx.x >> 8;
    int n = blockIdx.x & 255;
    int f = threadIdx.x;
    float v;
    if (n < N0_) v = d0[(b * F_ + f) * N0_ + n];
    else         v = d1[(b * F_ + f) * N1_ + (n - N0_)];
    g_x[(b * N_ + n) * F_ + f] = v;
    if (blockIdx.x < 18) {
        int zi = blockIdx.x * 256 + f;
        if (zi < 2048)       g_qs[zi] = 0.f;
        else if (zi < 4096)  g_ks[zi - 2048] = 0.f;
        else if (zi < 4352)  g_sum[zi - 4096] = 0.f;
        else                 g_sum2[zi - 4352] = 0.f;
    }
}

// ---------------- H = x @ W[r], fused q/k scores. grid (4,16,2) x 128 ----------------
__global__ __launch_bounds__(128) void gemm_H_mma(const float* __restrict__ W,
                                                  const float* __restrict__ q,
                                                  const float* __restrict__ kvec) {
    int r = blockIdx.z;
    const float* Bp = W + r * F_ * F_;
    float* C = g_H + (size_t)r * BN_ * F_;
    int m0 = blockIdx.y * 64, n0 = blockIdx.x * 64;
    __shared__ unsigned Asm[64 * ASTR], Bsm[16 * BSTR];
    int t = threadIdx.x, lane = t & 31, warp = t >> 5;
    int wm = (warp >> 1) * 32, wn = (warp & 1) * 32;
    float acc[2][4][4] = {};
    float4 ra[2], rb[2];
#pragma unroll
    for (int u = 0; u < 2; u++) {
        int idx = t * 2 + u;
        { int row = idx >> 2, c4 = (idx & 3) * 4; ra[u] = *(const float4*)&g_x[(m0 + row) * F_ + c4]; }
        { int row = idx >> 4, c4 = (idx & 15) * 4; rb[u] = *(const float4*)&Bp[row * F_ + n0 + c4]; }
    }
    for (int k0 = 0; k0 < F_; k0 += 16) {
        store_tiles(Asm, Bsm, ra, rb, t);
        __syncthreads();
        int kn = k0 + 16;
        if (kn < F_) {
#pragma unroll
            for (int u = 0; u < 2; u++) {
                int idx = t * 2 + u;
                { int row = idx >> 2, c4 = (idx & 3) * 4; ra[u] = *(const float4*)&g_x[(m0 + row) * F_ + kn + c4]; }
                { int row = idx >> 4, c4 = (idx & 15) * 4; rb[u] = *(const float4*)&Bp[(kn + row) * F_ + n0 + c4]; }
            }
        }
        compute_bk(Asm, Bsm, acc, lane, wm, wn);
        __syncthreads();
    }
    int g = lane >> 2, tg = lane & 3;
#pragma unroll
    for (int i = 0; i < 2; i++)
#pragma unroll
        for (int j = 0; j < 4; j++) {
            int row = m0 + wm + i * 16 + g, col = n0 + wn + j * 8 + tg * 2;
            *(float2*)&C[row * F_ + col] = make_float2(acc[i][j][0], acc[i][j][1]);
            *(float2*)&C[(row + 8) * F_ + col] = make_float2(acc[i][j][2], acc[i][j][3]);
        }
    // fused per-node q/k scores (partial over this block's 64 cols)
    float2 qv[4], kv[4];
#pragma unroll
    for (int j = 0; j < 4; j++) {
        int col = n0 + wn + j * 8 + tg * 2;
        qv[j] = *(const float2*)&q[col];
        kv[j] = *(const float2*)&kvec[col];
    }
#pragma unroll
    for (int i = 0; i < 2; i++) {
        float qp0 = 0, qp1 = 0, kp0 = 0, kp1 = 0;
#pragma unroll
        for (int j = 0; j < 4; j++) {
            qp0 += acc[i][j][0] * qv[j].x + acc[i][j][1] * qv[j].y;
            qp1 += acc[i][j][2] * qv[j].x + acc[i][j][3] * qv[j].y;
            kp0 += acc[i][j][0] * kv[j].x + acc[i][j][1] * kv[j].y;
            kp1 += acc[i][j][2] * kv[j].x + acc[i][j][3] * kv[j].y;
        }
#pragma unroll
        for (int o = 1; o < 4; o <<= 1) {
            qp0 += __shfl_xor_sync(0xffffffffu, qp0, o);
            qp1 += __shfl_xor_sync(0xffffffffu, qp1, o);
            kp0 += __shfl_xor_sync(0xffffffffu, kp0, o);
            kp1 += __shfl_xor_sync(0xffffffffu, kp1, o);
        }
        if (tg == 0) {
            int row = m0 + wm + i * 16 + g;
            atomicAdd(&g_qs[r * BN_ + row], qp0);
            atomicAdd(&g_qs[r * BN_ + row + 8], qp1);
            atomicAdd(&g_ks[r * BN_ + row], kp0);
            atomicAdd(&g_ks[r * BN_ + row + 8], kp1);
        }
    }
}

// ---------------- attention weights: one warp per dst node ----------------
__global__ void alpha_kernel() {
    int warp = (blockIdx.x * blockDim.x + threadIdx.x) >> 5;
    int lane = threadIdx.x & 31;
    int g = warp >> 8;
    int d = warp & 255;
    int dc = d >> 7;
    int nd = g * N_ + d;
    float qs0 = g_qs[nd];
    float qs1 = g_qs[BN_ + nd];
    float l[8];
    float mx = -INFINITY;
#pragma unroll
    for (int j = 0; j < 8; j++) {
        int s = j * 32 + lane;
        int r = (s >> 7) ^ dc;
        float ks = g_ks[r * BN_ + g * N_ + s];
        float qv = r ? qs1 : qs0;
        float v = qv + ks;
        v = v >= 0.0f ? v : 0.2f * v;
        if (s == d) v = -INFINITY;
        l[j] = v;
        mx = fmaxf(mx, v);
    }
#pragma unroll
    for (int o = 16; o; o >>= 1) mx = fmaxf(mx, __shfl_xor_sync(0xffffffffu, mx, o));
    float sum = 0.0f;
#pragma unroll
    for (int j = 0; j < 8; j++) { l[j] = expf(l[j] - mx); sum += l[j]; }
#pragma unroll
    for (int o = 16; o; o >>= 1) sum += __shfl_xor_sync(0xffffffffu, sum, o);
    float inv = 1.0f / (sum + 1e-16f);
#pragma unroll
    for (int j = 0; j < 8; j++) g_alpha[nd * N_ + j * 32 + lane] = l[j] * inv;
}

// ---------------- attention aggregation GEMM, relu(+conv_b). grid (4,2,8) x 128 ----------------
__global__ __launch_bounds__(128) void attn_gemm_mma(const float* __restrict__ convb) {
    int z = blockIdx.z;
    int gg = z >> 1, dc = z & 1;
    int m0 = blockIdx.y * 64, n0 = blockIdx.x * 64;
    const float* A = g_alpha + (size_t)(gg * N_ + dc * 128) * N_;
    float* C = g_msg1 + (size_t)(gg * N_ + dc * 128) * F_;
    __shared__ unsigned Asm[64 * ASTR], Bsm[16 * BSTR];
    int t = threadIdx.x, lane = t & 31, warp = t >> 5;
    int wm = (warp >> 1) * 32, wn = (warp & 1) * 32;
    float acc[2][4][4] = {};
    float4 ra[2], rb[2];
    auto loadg = [&](int k0) {
#pragma unroll
        for (int u = 0; u < 2; u++) {
            int idx = t * 2 + u;
            { int row = idx >> 2, c4 = (idx & 3) * 4; ra[u] = *(const float4*)&A[(m0 + row) * N_ + k0 + c4]; }
            {
                int row = idx >> 4, c4 = (idx & 15) * 4;
                int s = k0 + row;
                int rel = (s >> 7) ^ dc;
                rb[u] = *(const float4*)&g_H[((size_t)rel * BN_ + gg * N_ + s) * F_ + n0 + c4];
            }
        }
    };
    loadg(0);
    for (int k0 = 0; k0 < N_; k0 += 16) {
        store_tiles(Asm, Bsm, ra, rb, t);
        __syncthreads();
        if (k0 + 16 < N_) loadg(k0 + 16);
        compute_bk(Asm, Bsm, acc, lane, wm, wn);
        __syncthreads();
    }
    int g = lane >> 2, tg = lane & 3;
#pragma unroll
    for (int i = 0; i < 2; i++)
#pragma unroll
        for (int j = 0; j < 4; j++) {
            int row = m0 + wm + i * 16 + g, col = n0 + wn + j * 8 + tg * 2;
            float b0 = convb[col], b1 = convb[col + 1];
            float v0 = fmaxf(acc[i][j][0] + b0, 0.f), v1 = fmaxf(acc[i][j][1] + b1, 0.f);
            float v2 = fmaxf(acc[i][j][2] + b0, 0.f), v3 = fmaxf(acc[i][j][3] + b1, 0.f);
            *(float2*)&C[row * F_ + col] = make_float2(v0, v1);
            *(float2*)&C[(row + 8) * F_ + col] = make_float2(v2, v3);
        }
}

// ---------------- transpose lin_w [256 o][512 k] -> g_lwT [512 k][256 o] ----------------
__global__ void transpose_lw(const float* __restrict__ lw) {
    __shared__ float tt[32][33];
    int k0 = blockIdx.x * 32, o0 = blockIdx.y * 32;
    int tx = threadIdx.x, ty = threadIdx.y;
    for (int i = ty; i < 32; i += 8) tt[i][tx] = lw[(o0 + i) * (2 * F_) + k0 + tx];
    __syncthreads();
    for (int i = ty; i < 32; i += 8) g_lwT[(k0 + i) * F_ + o0 + tx] = tt[tx][i];
}

// ---------------- msg2 = [x, msg1] @ lwT + lin_b, fused BN partial sums. grid (4,16) x 128 ----------------
__global__ __launch_bounds__(128) void lin_gemm_mma(const float* __restrict__ linb) {
    int m0 = blockIdx.y * 64, n0 = blockIdx.x * 64;
    __shared__ unsigned Asm[64 * ASTR], Bsm[16 * BSTR];
    int t = threadIdx.x, lane = t & 31, warp = t >> 5;
    int wm = (warp >> 1) * 32, wn = (warp & 1) * 32;
    float acc[2][4][4] = {};
    float4 ra[2], rb[2];
    auto loadg = [&](int k0) {
        const float* Abase = (k0 < F_) ? g_x : g_msg1;
        int kk = (k0 < F_) ? k0 : k0 - F_;
#pragma unroll
        for (int u = 0; u < 2; u++) {
            int idx = t * 2 + u;
            { int row = idx >> 2, c4 = (idx & 3) * 4; ra[u] = *(const float4*)&Abase[(m0 + row) * F_ + kk + c4]; }
            { int row = idx >> 4, c4 = (idx & 15) * 4; rb[u] = *(const float4*)&g_lwT[(k0 + row) * F_ + n0 + c4]; }
        }
    };
    loadg(0);
    for (int k0 = 0; k0 < 2 * F_; k0 += 16) {
        store_tiles(Asm, Bsm, ra, rb, t);
        __syncthreads();
        if (k0 + 16 < 2 * F_) loadg(k0 + 16);
        compute_bk(Asm, Bsm, acc, lane, wm, wn);
        __syncthreads();
    }
    int g = lane >> 2, tg = lane & 3;
    float s0[4], s1[4], q0[4], q1[4];
#pragma unroll
    for (int j = 0; j < 4; j++) {
        int col = n0 + wn + j * 8 + tg * 2;
        float b0 = linb[col], b1 = linb[col + 1];
        float vs0 = 0, vs1 = 0, vq0 = 0, vq1 = 0;
#pragma unroll
        for (int i = 0; i < 2; i++) {
            int row = m0 + wm + i * 16 + g;
            float v0 = acc[i][j][0] + b0, v1 = acc[i][j][1] + b1;
            float v2 = acc[i][j][2] + b0, v3 = acc[i][j][3] + b1;
            *(float2*)&g_msg2[row * F_ + col] = make_float2(v0, v1);
            *(float2*)&g_msg2[(row + 8) * F_ + col] = make_float2(v2, v3);
            vs0 += v0 + v2; vs1 += v1 + v3;
            vq0 += v0 * v0 + v2 * v2; vq1 += v1 * v1 + v3 * v3;
        }
        s0[j] = vs0; s1[j] = vs1; q0[j] = vq0; q1[j] = vq1;
    }
#pragma unroll
    for (int o = 4; o < 32; o <<= 1) {
#pragma unroll
        for (int j = 0; j < 4; j++) {
            s0[j] += __shfl_xor_sync(0xffffffffu, s0[j], o);
            s1[j] += __shfl_xor_sync(0xffffffffu, s1[j], o);
            q0[j] += __shfl_xor_sync(0xffffffffu, q0[j], o);
            q1[j] += __shfl_xor_sync(0xffffffffu, q1[j], o);
        }
    }
    if (g == 0) {
#pragma unroll
        for (int j = 0; j < 4; j++) {
            int col = n0 + wn + j * 8 + tg * 2;
            atomicAdd(&g_sum[col], s0[j]);
            atomicAdd(&g_sum[col + 1], s1[j]);
            atomicAdd(&g_sum2[col], q0[j]);
            atomicAdd(&g_sum2[col + 1], q1[j]);
        }
    }
}

// ---------------- batchnorm stats finalize ----------------
__global__ void bn_pass2() {
    int c = threadIdx.x;
    float mu = g_sum[c] * (1.0f / BN_);
    float var = g_sum2[c] * (1.0f / BN_) - mu * mu;
    g_mu[c] = mu;
    g_rstd[c] = rsqrtf(var + 1e-5f);
}

// ---------------- residual apply (+zero accumulators for next layer) ----------------
__global__ void bn_apply(const float* __restrict__ bw, const float* __restrict__ bb) {
    int n = blockIdx.x;
    int c = threadIdx.x;
    int idx = n * F_ + c;
    g_x[idx] += bw[c] * (g_msg2[idx] - g_mu[c]) * g_rstd[c] + bb[c];
    if (blockIdx.x < 18) {
        int zi = blockIdx.x * 256 + c;
        if (zi < 2048)       g_qs[zi] = 0.f;
        else if (zi < 4096)  g_ks[zi - 2048] = 0.f;
        else if (zi < 4352)  g_sum[zi - 4096] = 0.f;
        else                 g_sum2[zi - 4352] = 0.f;
    }
}

// ---------------- unpack ----------------
__global__ void unpack_kernel(float* __restrict__ out) {
    int b = blockIdx.x >> 8;
    int n = blockIdx.x & 255;
    int f = threadIdx.x;
    float v = g_x[(b * N_ + n) * F_ + f];
    if (n < N0_) out[(b * F_ + f) * N0_ + n] = v;
    else         out[B_ * F_ * N0_ + (b * F_ + f) * N1_ + (n - N0_)] = v;
}

// ---------------- host ----------------
extern "C" void kernel_launch(void* const* d_in, const int* in_sizes, int n_in,
                              void* d_out, int out_size) {
    const float* desc0  = (const float*)d_in[0];
    const float* desc1  = (const float*)d_in[1];
    const float* conv_w = (const float*)d_in[2];
    const float* conv_q = (const float*)d_in[3];
    const float* conv_k = (const float*)d_in[4];
    const float* conv_b = (const float*)d_in[5];
    const float* lin_w  = (const float*)d_in[6];
    const float* lin_b  = (const float*)d_in[7];
    const float* bn_w   = (const float*)d_in[8];
    const float* bn_b   = (const float*)d_in[9];
    float* out = (float*)d_out;

    pack_kernel<<<BN_, F_>>>(desc0, desc1);

    for (int i = 0; i < L_; i++) {
        gemm_H_mma<<<dim3(4, 16, 2), 128>>>(conv_w + (size_t)i * 2 * F_ * F_,
                                            conv_q + i * F_, conv_k + i * F_);
        alpha_kernel<<<128, 256>>>();
        attn_gemm_mma<<<dim3(4, 2, 8), 128>>>(conv_b + i * F_);
        transpose_lw<<<dim3(16, 8), dim3(32, 8)>>>(lin_w + (size_t)i * F_ * 2 * F_);
        lin_gemm_mma<<<dim3(4, 16), 128>>>(lin_b + i * F_);
        bn_pass2<<<1, F_>>>();
        bn_apply<<<BN_, F_>>>(bn_w + i * F_, bn_b + i * F_);
    }

    unpack_kernel<<<BN_, F_>>>(out);
}

// round 6
// speedup vs baseline: 1.0066x; 1.0066x over previous
#include <cuda_runtime.h>
#include <math.h>

// ---------------- problem constants ----------------
#define B_   4
#define F_   256
#define N0_  128
#define N1_  128
#define N_   256        // nodes per graph
#define BN_  1024       // total nodes
#define L_   3

#define ASTR 20         // smem stride for A tile (64 x 16), conflict-free + 16B aligned
#define BSTR 72         // smem stride for B tile (16 x 64), conflict-free + 16B aligned

// ---------------- scratch (device globals; no allocation) ----------------
__device__ float g_x[BN_ * F_];
__device__ float g_H[2 * BN_ * F_];
__device__ float g_qs[2 * BN_];
__device__ float g_ks[2 * BN_];
__device__ float g_alpha[B_ * N_ * N_];
__device__ float g_msg1[BN_ * F_];
__device__ float g_msg2[BN_ * F_];
__device__ float g_lwT[2 * F_ * F_];
__device__ float g_sum[F_];
__device__ float g_sum2[F_];
__device__ float g_mu[F_];
__device__ float g_rstd[F_];

// ---------------- tf32 helpers ----------------
__device__ __forceinline__ unsigned f2tf(float f) {
    unsigned u;
    asm("cvt.rna.tf32.f32 %0, %1;" : "=r"(u) : "f"(f));
    return u;
}

__device__ __forceinline__ void mma8(float* d, const unsigned* a, const unsigned* b) {
    asm volatile(
        "mma.sync.aligned.m16n8k8.row.col.f32.tf32.tf32.f32 "
        "{%0,%1,%2,%3},{%4,%5,%6,%7},{%8,%9},{%0,%1,%2,%3};\n"
        : "+f"(d[0]), "+f"(d[1]), "+f"(d[2]), "+f"(d[3])
        : "r"(a[0]), "r"(a[1]), "r"(a[2]), "r"(a[3]), "r"(b[0]), "r"(b[1]));
}

// 64x64 block tile, 4 warps (warp tile 32x32 = 2 m-frags x 4 n-frags), BK=16
__device__ __forceinline__ void compute_bk(const unsigned* As, const unsigned* Bs,
                                           float acc[2][4][4], int lane, int wm, int wn) {
    int g = lane >> 2, tg = lane & 3;
#pragma unroll
    for (int s = 0; s < 2; s++) {
        int kb = s * 8;
        unsigned a[2][4], b[4][2];
#pragma unroll
        for (int i = 0; i < 2; i++) {
            int r0 = wm + i * 16 + g;
            a[i][0] = As[r0 * ASTR + kb + tg];
            a[i][1] = As[(r0 + 8) * ASTR + kb + tg];
            a[i][2] = As[r0 * ASTR + kb + tg + 4];
            a[i][3] = As[(r0 + 8) * ASTR + kb + tg + 4];
        }
#pragma unroll
        for (int j = 0; j < 4; j++) {
            b[j][0] = Bs[(kb + tg) * BSTR + wn + j * 8 + g];
            b[j][1] = Bs[(kb + tg + 4) * BSTR + wn + j * 8 + g];
        }
#pragma unroll
        for (int i = 0; i < 2; i++)
#pragma unroll
            for (int j = 0; j < 4; j++) mma8(acc[i][j], a[i], b[j]);
    }
}

__device__ __forceinline__ void store_tiles(unsigned* Asm, unsigned* Bsm,
                                            const float4* ra, const float4* rb, int t) {
#pragma unroll
    for (int u = 0; u < 2; u++) {
        int idx = t * 2 + u;
        {
            int row = idx >> 2, c4 = (idx & 3) * 4;
            uint4 w = make_uint4(f2tf(ra[u].x), f2tf(ra[u].y), f2tf(ra[u].z), f2tf(ra[u].w));
            *(uint4*)&Asm[row * ASTR + c4] = w;
        }
        {
            int row = idx >> 4, c4 = (idx & 15) * 4;
            uint4 w = make_uint4(f2tf(rb[u].x), f2tf(rb[u].y), f2tf(rb[u].z), f2tf(rb[u].w));
            *(uint4*)&Bsm[row * BSTR + c4] = w;
        }
    }
}

// ---------------- pack (+zero accumulators for layer 0) ----------------
__global__ void pack_kernel(const float* __restrict__ d0, const float* __restrict__ d1) {
    int b = blockIdx.x >> 8;
    int n = blockIdx.x & 255;
    int f = threadIdx.x;
    float v;
    if (n < N0_) v = d0[(b * F_ + f) * N0_ + n];
    else         v = d1[(b * F_ + f) * N1_ + (n - N0_)];
    g_x[(b * N_ + n) * F_ + f] = v;
    if (blockIdx.x < 18) {
        int zi = blockIdx.x * 256 + f;
        if (zi < 2048)       g_qs[zi] = 0.f;
        else if (zi < 4096)  g_ks[zi - 2048] = 0.f;
        else if (zi < 4352)  g_sum[zi - 4096] = 0.f;
        else                 g_sum2[zi - 4352] = 0.f;
    }
}

// ---------------- H = x @ W[r], fused q/k scores. grid (4,16,2) x 128 ----------------
__global__ __launch_bounds__(128) void gemm_H_mma(const float* __restrict__ W,
                                                  const float* __restrict__ q,
                                                  const float* __restrict__ kvec) {
    int r = blockIdx.z;
    const float* Bp = W + r * F_ * F_;
    float* C = g_H + (size_t)r * BN_ * F_;
    int m0 = blockIdx.y * 64, n0 = blockIdx.x * 64;
    __shared__ unsigned Asm[64 * ASTR], Bsm[16 * BSTR];
    int t = threadIdx.x, lane = t & 31, warp = t >> 5;
    int wm = (warp >> 1) * 32, wn = (warp & 1) * 32;
    float acc[2][4][4] = {};
    float4 ra[2], rb[2];
#pragma unroll
    for (int u = 0; u < 2; u++) {
        int idx = t * 2 + u;
        { int row = idx >> 2, c4 = (idx & 3) * 4; ra[u] = *(const float4*)&g_x[(m0 + row) * F_ + c4]; }
        { int row = idx >> 4, c4 = (idx & 15) * 4; rb[u] = *(const float4*)&Bp[row * F_ + n0 + c4]; }
    }
    for (int k0 = 0; k0 < F_; k0 += 16) {
        store_tiles(Asm, Bsm, ra, rb, t);
        __syncthreads();
        int kn = k0 + 16;
        if (kn < F_) {
#pragma unroll
            for (int u = 0; u < 2; u++) {
                int idx = t * 2 + u;
                { int row = idx >> 2, c4 = (idx & 3) * 4; ra[u] = *(const float4*)&g_x[(m0 + row) * F_ + kn + c4]; }
                { int row = idx >> 4, c4 = (idx & 15) * 4; rb[u] = *(const float4*)&Bp[(kn + row) * F_ + n0 + c4]; }
            }
        }
        compute_bk(Asm, Bsm, acc, lane, wm, wn);
        __syncthreads();
    }
    int g = lane >> 2, tg = lane & 3;
#pragma unroll
    for (int i = 0; i < 2; i++)
#pragma unroll
        for (int j = 0; j < 4; j++) {
            int row = m0 + wm + i * 16 + g, col = n0 + wn + j * 8 + tg * 2;
            *(float2*)&C[row * F_ + col] = make_float2(acc[i][j][0], acc[i][j][1]);
            *(float2*)&C[(row + 8) * F_ + col] = make_float2(acc[i][j][2], acc[i][j][3]);
        }
    // fused per-node q/k scores (partial over this block's 64 cols)
    float2 qv[4], kv[4];
#pragma unroll
    for (int j = 0; j < 4; j++) {
        int col = n0 + wn + j * 8 + tg * 2;
        qv[j] = *(const float2*)&q[col];
        kv[j] = *(const float2*)&kvec[col];
    }
#pragma unroll
    for (int i = 0; i < 2; i++) {
        float qp0 = 0, qp1 = 0, kp0 = 0, kp1 = 0;
#pragma unroll
        for (int j = 0; j < 4; j++) {
            qp0 += acc[i][j][0] * qv[j].x + acc[i][j][1] * qv[j].y;
            qp1 += acc[i][j][2] * qv[j].x + acc[i][j][3] * qv[j].y;
            kp0 += acc[i][j][0] * kv[j].x + acc[i][j][1] * kv[j].y;
            kp1 += acc[i][j][2] * kv[j].x + acc[i][j][3] * kv[j].y;
        }
#pragma unroll
        for (int o = 1; o < 4; o <<= 1) {
            qp0 += __shfl_xor_sync(0xffffffffu, qp0, o);
            qp1 += __shfl_xor_sync(0xffffffffu, qp1, o);
            kp0 += __shfl_xor_sync(0xffffffffu, kp0, o);
            kp1 += __shfl_xor_sync(0xffffffffu, kp1, o);
        }
        if (tg == 0) {
            int row = m0 + wm + i * 16 + g;
            atomicAdd(&g_qs[r * BN_ + row], qp0);
            atomicAdd(&g_qs[r * BN_ + row + 8], qp1);
            atomicAdd(&g_ks[r * BN_ + row], kp0);
            atomicAdd(&g_ks[r * BN_ + row + 8], kp1);
        }
    }
}

// ---------------- attention weights: one warp per dst node ----------------
__global__ void alpha_kernel() {
    int warp = (blockIdx.x * blockDim.x + threadIdx.x) >> 5;
    int lane = threadIdx.x & 31;
    int g = warp >> 8;
    int d = warp & 255;
    int dc = d >> 7;
    int nd = g * N_ + d;
    float qs0 = g_qs[nd];
    float qs1 = g_qs[BN_ + nd];
    float l[8];
    float mx = -INFINITY;
#pragma unroll
    for (int j = 0; j < 8; j++) {
        int s = j * 32 + lane;
        int r = (s >> 7) ^ dc;
        float ks = g_ks[r * BN_ + g * N_ + s];
        float qv = r ? qs1 : qs0;
        float v = qv + ks;
        v = v >= 0.0f ? v : 0.2f * v;
        if (s == d) v = -INFINITY;
        l[j] = v;
        mx = fmaxf(mx, v);
    }
#pragma unroll
    for (int o = 16; o; o >>= 1) mx = fmaxf(mx, __shfl_xor_sync(0xffffffffu, mx, o));
    float sum = 0.0f;
#pragma unroll
    for (int j = 0; j < 8; j++) { l[j] = expf(l[j] - mx); sum += l[j]; }
#pragma unroll
    for (int o = 16; o; o >>= 1) sum += __shfl_xor_sync(0xffffffffu, sum, o);
    float inv = 1.0f / (sum + 1e-16f);
#pragma unroll
    for (int j = 0; j < 8; j++) g_alpha[nd * N_ + j * 32 + lane] = l[j] * inv;
}

// ---------------- attention aggregation GEMM, relu(+conv_b). grid (4,2,8) x 128 ----------------
__global__ __launch_bounds__(128) void attn_gemm_mma(const float* __restrict__ convb) {
    int z = blockIdx.z;
    int gg = z >> 1, dc = z & 1;
    int m0 = blockIdx.y * 64, n0 = blockIdx.x * 64;
    const float* A = g_alpha + (size_t)(gg * N_ + dc * 128) * N_;
    float* C = g_msg1 + (size_t)(gg * N_ + dc * 128) * F_;
    __shared__ unsigned Asm[64 * ASTR], Bsm[16 * BSTR];
    int t = threadIdx.x, lane = t & 31, warp = t >> 5;
    int wm = (warp >> 1) * 32, wn = (warp & 1) * 32;
    float acc[2][4][4] = {};
    float4 ra[2], rb[2];
    auto loadg = [&](int k0) {
#pragma unroll
        for (int u = 0; u < 2; u++) {
            int idx = t * 2 + u;
            { int row = idx >> 2, c4 = (idx & 3) * 4; ra[u] = *(const float4*)&A[(m0 + row) * N_ + k0 + c4]; }
            {
                int row = idx >> 4, c4 = (idx & 15) * 4;
                int s = k0 + row;
                int rel = (s >> 7) ^ dc;
                rb[u] = *(const float4*)&g_H[((size_t)rel * BN_ + gg * N_ + s) * F_ + n0 + c4];
            }
        }
    };
    loadg(0);
    for (int k0 = 0; k0 < N_; k0 += 16) {
        store_tiles(Asm, Bsm, ra, rb, t);
        __syncthreads();
        if (k0 + 16 < N_) loadg(k0 + 16);
        compute_bk(Asm, Bsm, acc, lane, wm, wn);
        __syncthreads();
    }
    int g = lane >> 2, tg = lane & 3;
#pragma unroll
    for (int i = 0; i < 2; i++)
#pragma unroll
        for (int j = 0; j < 4; j++) {
            int row = m0 + wm + i * 16 + g, col = n0 + wn + j * 8 + tg * 2;
            float b0 = convb[col], b1 = convb[col + 1];
            float v0 = fmaxf(acc[i][j][0] + b0, 0.f), v1 = fmaxf(acc[i][j][1] + b1, 0.f);
            float v2 = fmaxf(acc[i][j][2] + b0, 0.f), v3 = fmaxf(acc[i][j][3] + b1, 0.f);
            *(float2*)&C[row * F_ + col] = make_float2(v0, v1);
            *(float2*)&C[(row + 8) * F_ + col] = make_float2(v2, v3);
        }
}

// ---------------- transpose lin_w [256 o][512 k] -> g_lwT [512 k][256 o] ----------------
__global__ void transpose_lw(const float* __restrict__ lw) {
    __shared__ float tt[32][33];
    int k0 = blockIdx.x * 32, o0 = blockIdx.y * 32;
    int tx = threadIdx.x, ty = threadIdx.y;
    for (int i = ty; i < 32; i += 8) tt[i][tx] = lw[(o0 + i) * (2 * F_) + k0 + tx];
    __syncthreads();
    for (int i = ty; i < 32; i += 8) g_lwT[(k0 + i) * F_ + o0 + tx] = tt[tx][i];
}

// ---------------- msg2 = [x, msg1] @ lwT + lin_b, fused BN partial sums. grid (4,16) x 128 ----------------
__global__ __launch_bounds__(128) void lin_gemm_mma(const float* __restrict__ linb) {
    int m0 = blockIdx.y * 64, n0 = blockIdx.x * 64;
    __shared__ unsigned Asm[64 * ASTR], Bsm[16 * BSTR];
    int t = threadIdx.x, lane = t & 31, warp = t >> 5;
    int wm = (warp >> 1) * 32, wn = (warp & 1) * 32;
    float acc[2][4][4] = {};
    float4 ra[2], rb[2];
    auto loadg = [&](int k0) {
        const float* Abase = (k0 < F_) ? g_x : g_msg1;
        int kk = (k0 < F_) ? k0 : k0 - F_;
#pragma unroll
        for (int u = 0; u < 2; u++) {
            int idx = t * 2 + u;
            { int row = idx >> 2, c4 = (idx & 3) * 4; ra[u] = *(const float4*)&Abase[(m0 + row) * F_ + kk + c4]; }
            { int row = idx >> 4, c4 = (idx & 15) * 4; rb[u] = *(const float4*)&g_lwT[(k0 + row) * F_ + n0 + c4]; }
        }
    };
    loadg(0);
    for (int k0 = 0; k0 < 2 * F_; k0 += 16) {
        store_tiles(Asm, Bsm, ra, rb, t);
        __syncthreads();
        if (k0 + 16 < 2 * F_) loadg(k0 + 16);
        compute_bk(Asm, Bsm, acc, lane, wm, wn);
        __syncthreads();
    }
    int g = lane >> 2, tg = lane & 3;
    float s0[4], s1[4], q0[4], q1[4];
#pragma unroll
    for (int j = 0; j < 4; j++) {
        int col = n0 + wn + j * 8 + tg * 2;
        float b0 = linb[col], b1 = linb[col + 1];
        float vs0 = 0, vs1 = 0, vq0 = 0, vq1 = 0;
#pragma unroll
        for (int i = 0; i < 2; i++) {
            int row = m0 + wm + i * 16 + g;
            float v0 = acc[i][j][0] + b0, v1 = acc[i][j][1] + b1;
            float v2 = acc[i][j][2] + b0, v3 = acc[i][j][3] + b1;
            *(float2*)&g_msg2[row * F_ + col] = make_float2(v0, v1);
            *(float2*)&g_msg2[(row + 8) * F_ + col] = make_float2(v2, v3);
            vs0 += v0 + v2; vs1 += v1 + v3;
            vq0 += v0 * v0 + v2 * v2; vq1 += v1 * v1 + v3 * v3;
        }
        s0[j] = vs0; s1[j] = vs1; q0[j] = vq0; q1[j] = vq1;
    }
#pragma unroll
    for (int o = 4; o < 32; o <<= 1) {
#pragma unroll
        for (int j = 0; j < 4; j++) {
            s0[j] += __shfl_xor_sync(0xffffffffu, s0[j], o);
            s1[j] += __shfl_xor_sync(0xffffffffu, s1[j], o);
            q0[j] += __shfl_xor_sync(0xffffffffu, q0[j], o);
            q1[j] += __shfl_xor_sync(0xffffffffu, q1[j], o);
        }
    }
    if (g == 0) {
#pragma unroll
        for (int j = 0; j < 4; j++) {
            int col = n0 + wn + j * 8 + tg * 2;
            atomicAdd(&g_sum[col], s0[j]);
            atomicAdd(&g_sum[col + 1], s1[j]);
            atomicAdd(&g_sum2[col], q0[j]);
            atomicAdd(&g_sum2[col + 1], q1[j]);
        }
    }
}

// ---------------- batchnorm stats finalize ----------------
__global__ void bn_pass2() {
    int c = threadIdx.x;
    float mu = g_sum[c] * (1.0f / BN_);
    float var = g_sum2[c] * (1.0f / BN_) - mu * mu;
    g_mu[c] = mu;
    g_rstd[c] = rsqrtf(var + 1e-5f);
}

// ---------------- residual apply (+zero accumulators for next layer) ----------------
__global__ void bn_apply(const float* __restrict__ bw, const float* __restrict__ bb) {
    int n = blockIdx.x;
    int c = threadIdx.x;
    int idx = n * F_ + c;
    g_x[idx] += bw[c] * (g_msg2[idx] - g_mu[c]) * g_rstd[c] + bb[c];
    if (blockIdx.x < 18) {
        int zi = blockIdx.x * 256 + c;
        if (zi < 2048)       g_qs[zi] = 0.f;
        else if (zi < 4096)  g_ks[zi - 2048] = 0.f;
        else if (zi < 4352)  g_sum[zi - 4096] = 0.f;
        else                 g_sum2[zi - 4352] = 0.f;
    }
}

// ---------------- unpack ----------------
__global__ void unpack_kernel(float* __restrict__ out) {
    int b = blockIdx.x >> 8;
    int n = blockIdx.x & 255;
    int f = threadIdx.x;
    float v = g_x[(b * N_ + n) * F_ + f];
    if (n < N0_) out[(b * F_ + f) * N0_ + n] = v;
    else         out[B_ * F_ * N0_ + (b * F_ + f) * N1_ + (n - N0_)] = v;
}

// ---------------- host ----------------
extern "C" void kernel_launch(void* const* d_in, const int* in_sizes, int n_in,
                              void* d_out, int out_size) {
    const float* desc0  = (const float*)d_in[0];
    const float* desc1  = (const float*)d_in[1];
    const float* conv_w = (const float*)d_in[2];
    const float* conv_q = (const float*)d_in[3];
    const float* conv_k = (const float*)d_in[4];
    const float* conv_b = (const float*)d_in[5];
    const float* lin_w  = (const float*)d_in[6];
    const float* lin_b  = (const float*)d_in[7];
    const float* bn_w   = (const float*)d_in[8];
    const float* bn_b   = (const float*)d_in[9];
    float* out = (float*)d_out;

    pack_kernel<<<BN_, F_>>>(desc0, desc1);

    for (int i = 0; i < L_; i++) {
        gemm_H_mma<<<dim3(4, 16, 2), 128>>>(conv_w + (size_t)i * 2 * F_ * F_,
                                            conv_q + i * F_, conv_k + i * F_);
        alpha_kernel<<<128, 256>>>();
        attn_gemm_mma<<<dim3(4, 2, 8), 128>>>(conv_b + i * F_);
        transpose_lw<<<dim3(16, 8), dim3(32, 8)>>>(lin_w + (size_t)i * F_ * 2 * F_);
        lin_gemm_mma<<<dim3(4, 16), 128>>>(lin_b + i * F_);
        bn_pass2<<<1, F_>>>();
        bn_apply<<<BN_, F_>>>(bn_w + i * F_, bn_b + i * F_);
    }

    unpack_kernel<<<BN_, F_>>>(out);
}

// round 7
// speedup vs baseline: 1.0115x; 1.0048x over previous
#include <cuda_runtime.h>
#include <math.h>

// ---------------- problem constants ----------------
#define B_   4
#define F_   256
#define N0_  128
#define N1_  128
#define N_   256        // nodes per graph
#define BN_  1024       // total nodes
#define L_   3

#define ASTR 20         // smem stride for A tile (64 x 16), conflict-free + 16B aligned
#define BSTR 72         // smem stride for B tile (16 x 64), conflict-free + 16B aligned

// ---------------- scratch (device globals; no allocation) ----------------
__device__ float g_x[BN_ * F_];
__device__ float g_H[2 * BN_ * F_];
__device__ float g_qs[2 * BN_];
__device__ float g_ks[2 * BN_];
__device__ float g_alpha[B_ * N_ * N_];
__device__ float g_msg1[BN_ * F_];
__device__ float g_msg2[BN_ * F_];
__device__ float g_lwT[2 * F_ * F_];
__device__ float g_sum[F_];
__device__ float g_sum2[F_];
__device__ float g_mu[F_];
__device__ float g_rstd[F_];

// ---------------- tf32 helpers ----------------
__device__ __forceinline__ unsigned f2tf(float f) {
    unsigned u;
    asm("cvt.rna.tf32.f32 %0, %1;" : "=r"(u) : "f"(f));
    return u;
}

__device__ __forceinline__ void mma8(float* d, const unsigned* a, const unsigned* b) {
    asm volatile(
        "mma.sync.aligned.m16n8k8.row.col.f32.tf32.tf32.f32 "
        "{%0,%1,%2,%3},{%4,%5,%6,%7},{%8,%9},{%0,%1,%2,%3};\n"
        : "+f"(d[0]), "+f"(d[1]), "+f"(d[2]), "+f"(d[3])
        : "r"(a[0]), "r"(a[1]), "r"(a[2]), "r"(a[3]), "r"(b[0]), "r"(b[1]));
}

// 64x64 block tile, 4 warps (warp tile 32x32 = 2 m-frags x 4 n-frags), BK=16
__device__ __forceinline__ void compute_bk(const unsigned* As, const unsigned* Bs,
                                           float acc[2][4][4], int lane, int wm, int wn) {
    int g = lane >> 2, tg = lane & 3;
#pragma unroll
    for (int s = 0; s < 2; s++) {
        int kb = s * 8;
        unsigned a[2][4], b[4][2];
#pragma unroll
        for (int i = 0; i < 2; i++) {
            int r0 = wm + i * 16 + g;
            a[i][0] = As[r0 * ASTR + kb + tg];
            a[i][1] = As[(r0 + 8) * ASTR + kb + tg];
            a[i][2] = As[r0 * ASTR + kb + tg + 4];
            a[i][3] = As[(r0 + 8) * ASTR + kb + tg + 4];
        }
#pragma unroll
        for (int j = 0; j < 4; j++) {
            b[j][0] = Bs[(kb + tg) * BSTR + wn + j * 8 + g];
            b[j][1] = Bs[(kb + tg + 4) * BSTR + wn + j * 8 + g];
        }
#pragma unroll
        for (int i = 0; i < 2; i++)
#pragma unroll
            for (int j = 0; j < 4; j++) mma8(acc[i][j], a[i], b[j]);
    }
}

__device__ __forceinline__ void store_tiles(unsigned* Asm, unsigned* Bsm,
                                            const float4* ra, const float4* rb, int t) {
#pragma unroll
    for (int u = 0; u < 2; u++) {
        int idx = t * 2 + u;
        {
            int row = idx >> 2, c4 = (idx & 3) * 4;
            uint4 w = make_uint4(f2tf(ra[u].x), f2tf(ra[u].y), f2tf(ra[u].z), f2tf(ra[u].w));
            *(uint4*)&Asm[row * ASTR + c4] = w;
        }
        {
            int row = idx >> 4, c4 = (idx & 15) * 4;
            uint4 w = make_uint4(f2tf(rb[u].x), f2tf(rb[u].y), f2tf(rb[u].z), f2tf(rb[u].w));
            *(uint4*)&Bsm[row * BSTR + c4] = w;
        }
    }
}

// ---------------- pack (+zero accumulators for layer 0) ----------------
__global__ void pack_kernel(const float* __restrict__ d0, const float* __restrict__ d1) {
    int b = blockIdx.x >> 8;
    int n = blockIdx.x & 255;
    int f = threadIdx.x;
    float v;
    if (n < N0_) v = d0[(b * F_ + f) * N0_ + n];
    else         v = d1[(b * F_ + f) * N1_ + (n - N0_)];
    g_x[(b * N_ + n) * F_ + f] = v;
    if (blockIdx.x < 18) {
        int zi = blockIdx.x * 256 + f;
        if (zi < 2048)       g_qs[zi] = 0.f;
        else if (zi < 4096)  g_ks[zi - 2048] = 0.f;
        else if (zi < 4352)  g_sum[zi - 4096] = 0.f;
        else                 g_sum2[zi - 4352] = 0.f;
    }
}

// ---------------- H = x @ W[r], fused q/k scores. grid (4,16,2) x 128 ----------------
__global__ __launch_bounds__(128) void gemm_H_mma(const float* __restrict__ W,
                                                  const float* __restrict__ q,
                                                  const float* __restrict__ kvec) {
    int r = blockIdx.z;
    const float* Bp = W + r * F_ * F_;
    float* C = g_H + (size_t)r * BN_ * F_;
    int m0 = blockIdx.y * 64, n0 = blockIdx.x * 64;
    __shared__ unsigned Asm[64 * ASTR], Bsm[16 * BSTR];
    int t = threadIdx.x, lane = t & 31, warp = t >> 5;
    int wm = (warp >> 1) * 32, wn = (warp & 1) * 32;
    float acc[2][4][4] = {};
    float4 ra[2], rb[2];
#pragma unroll
    for (int u = 0; u < 2; u++) {
        int idx = t * 2 + u;
        { int row = idx >> 2, c4 = (idx & 3) * 4; ra[u] = *(const float4*)&g_x[(m0 + row) * F_ + c4]; }
        { int row = idx >> 4, c4 = (idx & 15) * 4; rb[u] = *(const float4*)&Bp[row * F_ + n0 + c4]; }
    }
    for (int k0 = 0; k0 < F_; k0 += 16) {
        store_tiles(Asm, Bsm, ra, rb, t);
        __syncthreads();
        int kn = k0 + 16;
        if (kn < F_) {
#pragma unroll
            for (int u = 0; u < 2; u++) {
                int idx = t * 2 + u;
                { int row = idx >> 2, c4 = (idx & 3) * 4; ra[u] = *(const float4*)&g_x[(m0 + row) * F_ + kn + c4]; }
                { int row = idx >> 4, c4 = (idx & 15) * 4; rb[u] = *(const float4*)&Bp[(kn + row) * F_ + n0 + c4]; }
            }
        }
        compute_bk(Asm, Bsm, acc, lane, wm, wn);
        __syncthreads();
    }
    int g = lane >> 2, tg = lane & 3;
#pragma unroll
    for (int i = 0; i < 2; i++)
#pragma unroll
        for (int j = 0; j < 4; j++) {
            int row = m0 + wm + i * 16 + g, col = n0 + wn + j * 8 + tg * 2;
            *(float2*)&C[row * F_ + col] = make_float2(acc[i][j][0], acc[i][j][1]);
            *(float2*)&C[(row + 8) * F_ + col] = make_float2(acc[i][j][2], acc[i][j][3]);
        }
    // fused per-node q/k scores (partial over this block's 64 cols)
    float2 qv[4], kv[4];
#pragma unroll
    for (int j = 0; j < 4; j++) {
        int col = n0 + wn + j * 8 + tg * 2;
        qv[j] = *(const float2*)&q[col];
        kv[j] = *(const float2*)&kvec[col];
    }
#pragma unroll
    for (int i = 0; i < 2; i++) {
        float qp0 = 0, qp1 = 0, kp0 = 0, kp1 = 0;
#pragma unroll
        for (int j = 0; j < 4; j++) {
            qp0 += acc[i][j][0] * qv[j].x + acc[i][j][1] * qv[j].y;
            qp1 += acc[i][j][2] * qv[j].x + acc[i][j][3] * qv[j].y;
            kp0 += acc[i][j][0] * kv[j].x + acc[i][j][1] * kv[j].y;
            kp1 += acc[i][j][2] * kv[j].x + acc[i][j][3] * kv[j].y;
        }
#pragma unroll
        for (int o = 1; o < 4; o <<= 1) {
            qp0 += __shfl_xor_sync(0xffffffffu, qp0, o);
            qp1 += __shfl_xor_sync(0xffffffffu, qp1, o);
            kp0 += __shfl_xor_sync(0xffffffffu, kp0, o);
            kp1 += __shfl_xor_sync(0xffffffffu, kp1, o);
        }
        if (tg == 0) {
            int row = m0 + wm + i * 16 + g;
            atomicAdd(&g_qs[r * BN_ + row], qp0);
            atomicAdd(&g_qs[r * BN_ + row + 8], qp1);
            atomicAdd(&g_ks[r * BN_ + row], kp0);
            atomicAdd(&g_ks[r * BN_ + row + 8], kp1);
        }
    }
}

// ---------------- attention weights: one warp per dst node ----------------
__global__ void alpha_kernel() {
    int warp = (blockIdx.x * blockDim.x + threadIdx.x) >> 5;
    int lane = threadIdx.x & 31;
    int g = warp >> 8;
    int d = warp & 255;
    int dc = d >> 7;
    int nd = g * N_ + d;
    float qs0 = g_qs[nd];
    float qs1 = g_qs[BN_ + nd];
    float l[8];
    float mx = -INFINITY;
#pragma unroll
    for (int j = 0; j < 8; j++) {
        int s = j * 32 + lane;
        int r = (s >> 7) ^ dc;
        float ks = g_ks[r * BN_ + g * N_ + s];
        float qv = r ? qs1 : qs0;
        float v = qv + ks;
        v = v >= 0.0f ? v : 0.2f * v;
        if (s == d) v = -INFINITY;
        l[j] = v;
        mx = fmaxf(mx, v);
    }
#pragma unroll
    for (int o = 16; o; o >>= 1) mx = fmaxf(mx, __shfl_xor_sync(0xffffffffu, mx, o));
    float sum = 0.0f;
#pragma unroll
    for (int j = 0; j < 8; j++) { l[j] = expf(l[j] - mx); sum += l[j]; }
#pragma unroll
    for (int o = 16; o; o >>= 1) sum += __shfl_xor_sync(0xffffffffu, sum, o);
    float inv = 1.0f / (sum + 1e-16f);
#pragma unroll
    for (int j = 0; j < 8; j++) g_alpha[nd * N_ + j * 32 + lane] = l[j] * inv;
}

// ---------------- attention aggregation GEMM, relu(+conv_b). grid (4,2,8) x 128 ----------------
__global__ __launch_bounds__(128) void attn_gemm_mma(const float* __restrict__ convb) {
    int z = blockIdx.z;
    int gg = z >> 1, dc = z & 1;
    int m0 = blockIdx.y * 64, n0 = blockIdx.x * 64;
    const float* A = g_alpha + (size_t)(gg * N_ + dc * 128) * N_;
    float* C = g_msg1 + (size_t)(gg * N_ + dc * 128) * F_;
    __shared__ unsigned Asm[64 * ASTR], Bsm[16 * BSTR];
    int t = threadIdx.x, lane = t & 31, warp = t >> 5;
    int wm = (warp >> 1) * 32, wn = (warp & 1) * 32;
    float acc[2][4][4] = {};
    float4 ra[2], rb[2];
    auto loadg = [&](int k0) {
#pragma unroll
        for (int u = 0; u < 2; u++) {
            int idx = t * 2 + u;
            { int row = idx >> 2, c4 = (idx & 3) * 4; ra[u] = *(const float4*)&A[(m0 + row) * N_ + k0 + c4]; }
            {
                int row = idx >> 4, c4 = (idx & 15) * 4;
                int s = k0 + row;
                int rel = (s >> 7) ^ dc;
                rb[u] = *(const float4*)&g_H[((size_t)rel * BN_ + gg * N_ + s) * F_ + n0 + c4];
            }
        }
    };
    loadg(0);
    for (int k0 = 0; k0 < N_; k0 += 16) {
        store_tiles(Asm, Bsm, ra, rb, t);
        __syncthreads();
        if (k0 + 16 < N_) loadg(k0 + 16);
        compute_bk(Asm, Bsm, acc, lane, wm, wn);
        __syncthreads();
    }
    int g = lane >> 2, tg = lane & 3;
#pragma unroll
    for (int i = 0; i < 2; i++)
#pragma unroll
        for (int j = 0; j < 4; j++) {
            int row = m0 + wm + i * 16 + g, col = n0 + wn + j * 8 + tg * 2;
            float b0 = convb[col], b1 = convb[col + 1];
            float v0 = fmaxf(acc[i][j][0] + b0, 0.f), v1 = fmaxf(acc[i][j][1] + b1, 0.f);
            float v2 = fmaxf(acc[i][j][2] + b0, 0.f), v3 = fmaxf(acc[i][j][3] + b1, 0.f);
            *(float2*)&C[row * F_ + col] = make_float2(v0, v1);
            *(float2*)&C[(row + 8) * F_ + col] = make_float2(v2, v3);
        }
}

// ---------------- transpose lin_w [256 o][512 k] -> g_lwT [512 k][256 o] ----------------
__global__ void transpose_lw(const float* __restrict__ lw) {
    __shared__ float tt[32][33];
    int k0 = blockIdx.x * 32, o0 = blockIdx.y * 32;
    int tx = threadIdx.x, ty = threadIdx.y;
    for (int i = ty; i < 32; i += 8) tt[i][tx] = lw[(o0 + i) * (2 * F_) + k0 + tx];
    __syncthreads();
    for (int i = ty; i < 32; i += 8) g_lwT[(k0 + i) * F_ + o0 + tx] = tt[tx][i];
}

// ---------------- msg2 = [x, msg1] @ lwT + lin_b, fused BN partial sums. grid (4,16) x 128 ----------------
__global__ __launch_bounds__(128) void lin_gemm_mma(const float* __restrict__ linb) {
    int m0 = blockIdx.y * 64, n0 = blockIdx.x * 64;
    __shared__ unsigned Asm[64 * ASTR], Bsm[16 * BSTR];
    int t = threadIdx.x, lane = t & 31, warp = t >> 5;
    int wm = (warp >> 1) * 32, wn = (warp & 1) * 32;
    float acc[2][4][4] = {};
    float4 ra[2], rb[2];
    auto loadg = [&](int k0) {
        const float* Abase = (k0 < F_) ? g_x : g_msg1;
        int kk = (k0 < F_) ? k0 : k0 - F_;
#pragma unroll
        for (int u = 0; u < 2; u++) {
            int idx = t * 2 + u;
            { int row = idx >> 2, c4 = (idx & 3) * 4; ra[u] = *(const float4*)&Abase[(m0 + row) * F_ + kk + c4]; }
            { int row = idx >> 4, c4 = (idx & 15) * 4; rb[u] = *(const float4*)&g_lwT[(k0 + row) * F_ + n0 + c4]; }
        }
    };
    loadg(0);
    for (int k0 = 0; k0 < 2 * F_; k0 += 16) {
        store_tiles(Asm, Bsm, ra, rb, t);
        __syncthreads();
        if (k0 + 16 < 2 * F_) loadg(k0 + 16);
        compute_bk(Asm, Bsm, acc, lane, wm, wn);
        __syncthreads();
    }
    int g = lane >> 2, tg = lane & 3;
    float s0[4], s1[4], q0[4], q1[4];
#pragma unroll
    for (int j = 0; j < 4; j++) {
        int col = n0 + wn + j * 8 + tg * 2;
        float b0 = linb[col], b1 = linb[col + 1];
        float vs0 = 0, vs1 = 0, vq0 = 0, vq1 = 0;
#pragma unroll
        for (int i = 0; i < 2; i++) {
            int row = m0 + wm + i * 16 + g;
            float v0 = acc[i][j][0] + b0, v1 = acc[i][j][1] + b1;
            float v2 = acc[i][j][2] + b0, v3 = acc[i][j][3] + b1;
            *(float2*)&g_msg2[row * F_ + col] = make_float2(v0, v1);
            *(float2*)&g_msg2[(row + 8) * F_ + col] = make_float2(v2, v3);
            vs0 += v0 + v2; vs1 += v1 + v3;
            vq0 += v0 * v0 + v2 * v2; vq1 += v1 * v1 + v3 * v3;
        }
        s0[j] = vs0; s1[j] = vs1; q0[j] = vq0; q1[j] = vq1;
    }
#pragma unroll
    for (int o = 4; o < 32; o <<= 1) {
#pragma unroll
        for (int j = 0; j < 4; j++) {
            s0[j] += __shfl_xor_sync(0xffffffffu, s0[j], o);
            s1[j] += __shfl_xor_sync(0xffffffffu, s1[j], o);
            q0[j] += __shfl_xor_sync(0xffffffffu, q0[j], o);
            q1[j] += __shfl_xor_sync(0xffffffffu, q1[j], o);
        }
    }
    if (g == 0) {
#pragma unroll
        for (int j = 0; j < 4; j++) {
            int col = n0 + wn + j * 8 + tg * 2;
            atomicAdd(&g_sum[col], s0[j]);
            atomicAdd(&g_sum[col + 1], s1[j]);
            atomicAdd(&g_sum2[col], q0[j]);
            atomicAdd(&g_sum2[col + 1], q1[j]);
        }
    }
}

// ---------------- batchnorm stats finalize ----------------
__global__ void bn_pass2() {
    int c = threadIdx.x;
    float mu = g_sum[c] * (1.0f / BN_);
    float var = g_sum2[c] * (1.0f / BN_) - mu * mu;
    g_mu[c] = mu;
    g_rstd[c] = rsqrtf(var + 1e-5f);
}

// ---------------- residual apply (+zero accumulators for next layer) ----------------
__global__ void bn_apply(const float* __restrict__ bw, const float* __restrict__ bb) {
    int n = blockIdx.x;
    int c = threadIdx.x;
    int idx = n * F_ + c;
    g_x[idx] += bw[c] * (g_msg2[idx] - g_mu[c]) * g_rstd[c] + bb[c];
    if (blockIdx.x < 18) {
        int zi = blockIdx.x * 256 + c;
        if (zi < 2048)       g_qs[zi] = 0.f;
        else if (zi < 4096)  g_ks[zi - 2048] = 0.f;
        else if (zi < 4352)  g_sum[zi - 4096] = 0.f;
        else                 g_sum2[zi - 4352] = 0.f;
    }
}

// ---------------- unpack ----------------
__global__ void unpack_kernel(float* __restrict__ out) {
    int b = blockIdx.x >> 8;
    int n = blockIdx.x & 255;
    int f = threadIdx.x;
    float v = g_x[(b * N_ + n) * F_ + f];
    if (n < N0_) out[(b * F_ + f) * N0_ + n] = v;
    else         out[B_ * F_ * N0_ + (b * F_ + f) * N1_ + (n - N0_)] = v;
}

// ---------------- host ----------------
extern "C" void kernel_launch(void* const* d_in, const int* in_sizes, int n_in,
                              void* d_out, int out_size) {
    const float* desc0  = (const float*)d_in[0];
    const float* desc1  = (const float*)d_in[1];
    const float* conv_w = (const float*)d_in[2];
    const float* conv_q = (const float*)d_in[3];
    const float* conv_k = (const float*)d_in[4];
    const float* conv_b = (const float*)d_in[5];
    const float* lin_w  = (const float*)d_in[6];
    const float* lin_b  = (const float*)d_in[7];
    const float* bn_w   = (const float*)d_in[8];
    const float* bn_b   = (const float*)d_in[9];
    float* out = (float*)d_out;

    pack_kernel<<<BN_, F_>>>(desc0, desc1);

    for (int i = 0; i < L_; i++) {
        gemm_H_mma<<<dim3(4, 16, 2), 128>>>(conv_w + (size_t)i * 2 * F_ * F_,
                                            conv_q + i * F_, conv_k + i * F_);
        alpha_kernel<<<128, 256>>>();
        attn_gemm_mma<<<dim3(4, 2, 8), 128>>>(conv_b + i * F_);
        transpose_lw<<<dim3(16, 8), dim3(32, 8)>>>(lin_w + (size_t)i * F_ * 2 * F_);
        lin_gemm_mma<<<dim3(4, 16), 128>>>(lin_b + i * F_);
        bn_pass2<<<1, F_>>>();
        bn_apply<<<BN_, F_>>>(bn_w + i * F_, bn_b + i * F_);
    }

    unpack_kernel<<<BN_, F_>>>(out);
}